// round 3
// baseline (speedup 1.0000x reference)
#include <cuda_runtime.h>

#define C     256
#define H     128
#define W     128
#define GK2   72
#define KK    9
#define CPG   32            // C / GROUP
#define N_MAX 32
#define BN_EPS 1e-5f

// scratch (no allocations allowed)
__device__ float g_pooled[N_MAX * C];
__device__ float g_wk[N_MAX * GK2];

// ---------------------------------------------------------------------------
// Kernel 1: global average pool. One block per (n,c) plane (128x128 fp32).
// ---------------------------------------------------------------------------
__global__ __launch_bounds__(256) void pool_kernel(const float* __restrict__ x) {
    int plane = blockIdx.x;
    const float4* p = (const float4*)(x + (size_t)plane * (H * W));
    float s = 0.f;
#pragma unroll 4
    for (int i = threadIdx.x; i < (H * W) / 4; i += 256) {
        float4 v = p[i];
        s += (v.x + v.y) + (v.z + v.w);
    }
#pragma unroll
    for (int o = 16; o; o >>= 1) s += __shfl_down_sync(0xffffffffu, s, o);
    __shared__ float ws[8];
    int warp = threadIdx.x >> 5, lane = threadIdx.x & 31;
    if (lane == 0) ws[warp] = s;
    __syncthreads();
    if (threadIdx.x == 0) {
        float t = 0.f;
#pragma unroll
        for (int i = 0; i < 8; ++i) t += ws[i];
        g_pooled[plane] = t * (1.0f / (H * W));
    }
}

// ---------------------------------------------------------------------------
// Kernel 2: lf = pooled @ conv_w^T ; gate; BN; softmax over 9 taps per group.
// One block per sample n, 128 threads (72 active for the per-tap work).
// ---------------------------------------------------------------------------
__global__ __launch_bounds__(128) void weight_kernel(
    const float* __restrict__ conv_w, const float* __restrict__ gate_w,
    const float* __restrict__ gamma,  const float* __restrict__ beta,
    const float* __restrict__ mean,   const float* __restrict__ var) {
    int n = blockIdx.x;
    __shared__ float sp[C];
    __shared__ float slf[GK2];
    __shared__ float sbn[GK2];
    for (int i = threadIdx.x; i < C; i += 128) sp[i] = g_pooled[n * C + i];
    __syncthreads();
    int t = threadIdx.x;
    if (t < GK2) {
        const float* wr = conv_w + t * C;
        float acc = 0.f;
#pragma unroll 8
        for (int k = 0; k < C; ++k) acc = fmaf(sp[k], wr[k], acc);
        slf[t] = acc;
    }
    __syncthreads();
    if (t < GK2) {
        const float* gr = gate_w + t * GK2;
        float acc = 0.f;
#pragma unroll 8
        for (int k = 0; k < GK2; ++k) acc = fmaf(slf[k], gr[k], acc);
        float v = slf[t];
        float gated = v * (1.0f / (1.0f + expf(-acc)));
        sbn[t] = (gated - mean[t]) * (gamma[t] * rsqrtf(var[t] + BN_EPS)) + beta[t];
    }
    __syncthreads();
    if (t < GK2) {
        int g = t / KK;
        float mx = -1e30f;
#pragma unroll
        for (int k = 0; k < KK; ++k) mx = fmaxf(mx, sbn[g * KK + k]);
        float ssum = 0.f;
#pragma unroll
        for (int k = 0; k < KK; ++k) ssum += expf(sbn[g * KK + k] - mx);
        g_wk[n * GK2 + t] = expf(sbn[t] - mx) / ssum;
    }
}

// ---------------------------------------------------------------------------
// Kernel 3: reflect-padded 3x3 weighted average + residual.
// One block per (n,c) plane. 8 warps; each warp owns 16 rows, a full 128-wide
// row per warp (32 lanes x float4). 1 LDG.128 per row via rolling window;
// horizontal neighbors via shfl; reflect edges in-register.
// ---------------------------------------------------------------------------
struct RowT { float4 v; float L, R; };

__global__ __launch_bounds__(256) void stencil_kernel(
    const float* __restrict__ x, float* __restrict__ out, long long half) {
    int plane = blockIdx.x;            // n*C + ch
    int n  = plane / C;
    int ch = plane - n * C;
    int g  = ch / CPG;
    const float* wp = &g_wk[n * GK2 + g * KK];
    float w0 = wp[0], w1 = wp[1], w2 = wp[2];
    float w3 = wp[3], w4 = wp[4], w5 = wp[5];
    float w6 = wp[6], w7 = wp[7], w8 = wp[8];

    const float4* in4 = (const float4*)(x + (size_t)plane * (H * W));
    float4* lo4 = (float4*)out + (size_t)plane * (H * W / 4);
    float4* hi4 = (float4*)(out + half) + (size_t)plane * (H * W / 4);

    int warp = threadIdx.x >> 5, lane = threadIdx.x & 31;
    int y0 = warp * 16;

    auto load = [&](int y) {
        RowT r;
        r.v = in4[y * (W / 4) + lane];
        r.L = __shfl_up_sync(0xffffffffu, r.v.w, 1);
        r.R = __shfl_down_sync(0xffffffffu, r.v.x, 1);
        if (lane == 0)  r.L = r.v.y;   // reflect col -1 -> col 1
        if (lane == 31) r.R = r.v.z;   // reflect col W -> col W-2
        return r;
    };

    RowT pm = load(y0 == 0 ? 1 : y0 - 1);   // reflect row -1 -> row 1
    RowT cm = load(y0);

#pragma unroll 4
    for (int y = y0; y < y0 + 16; ++y) {
        RowT nx = load(y == H - 1 ? H - 2 : y + 1);  // reflect row H -> H-2
        float4 a;
        a.x = w0 * pm.L   + w1 * pm.v.x + w2 * pm.v.y
            + w3 * cm.L   + w4 * cm.v.x + w5 * cm.v.y
            + w6 * nx.L   + w7 * nx.v.x + w8 * nx.v.y;
        a.y = w0 * pm.v.x + w1 * pm.v.y + w2 * pm.v.z
            + w3 * cm.v.x + w4 * cm.v.y + w5 * cm.v.z
            + w6 * nx.v.x + w7 * nx.v.y + w8 * nx.v.z;
        a.z = w0 * pm.v.y + w1 * pm.v.z + w2 * pm.v.w
            + w3 * cm.v.y + w4 * cm.v.z + w5 * cm.v.w
            + w6 * nx.v.y + w7 * nx.v.z + w8 * nx.v.w;
        a.w = w0 * pm.v.z + w1 * pm.v.w + w2 * pm.R
            + w3 * cm.v.z + w4 * cm.v.w + w5 * cm.R
            + w6 * nx.v.z + w7 * nx.v.w + w8 * nx.R;
        int o = y * (W / 4) + lane;
        lo4[o] = a;
        float4 hv;
        hv.x = cm.v.x - a.x;
        hv.y = cm.v.y - a.y;
        hv.z = cm.v.z - a.z;
        hv.w = cm.v.w - a.w;
        hi4[o] = hv;
        pm = cm;
        cm = nx;
    }
}

// ---------------------------------------------------------------------------
extern "C" void kernel_launch(void* const* d_in, const int* in_sizes, int n_in,
                              void* d_out, int out_size) {
    const float* x      = (const float*)d_in[0];
    const float* conv_w = (const float*)d_in[1];
    const float* gate_w = (const float*)d_in[2];
    const float* gamma  = (const float*)d_in[3];
    const float* beta   = (const float*)d_in[4];
    const float* mean   = (const float*)d_in[5];
    const float* var    = (const float*)d_in[6];
    int n = in_sizes[0] / (C * H * W);

    pool_kernel<<<n * C, 256>>>(x);
    weight_kernel<<<n, 128>>>(conv_w, gate_w, gamma, beta, mean, var);
    long long half = (long long)out_size / 2;
    stencil_kernel<<<n * C, 256>>>(x, (float*)d_out, half);
}